// round 6
// baseline (speedup 1.0000x reference)
#include <cuda_runtime.h>
#include <math.h>

#define N_ROWS 8192
#define F_IN   512
#define H_DIM  256
#define W_DIM  64

// Scratch (device globals: allocation-free per harness rules)
static __device__ float g_h1[N_ROWS * H_DIM];   // 8 MB
static __device__ float g_h2[N_ROWS * H_DIM];   // 8 MB
static __device__ float g_q [N_ROWS * W_DIM];   // 2 MB

// ---------------------------------------------------------------------------
// f32x2 packed helpers (FFMA2: 2 MACs per instruction on sm_103a)
// ---------------------------------------------------------------------------
__device__ __forceinline__ unsigned long long pack_ff(float a) {
    unsigned long long r;
    unsigned int u = __float_as_uint(a);
    asm("mov.b64 %0, {%1, %1};" : "=l"(r) : "r"(u));
    return r;
}
__device__ __forceinline__ void ffma2(unsigned long long &c,
                                      unsigned long long a,
                                      unsigned long long b) {
    asm("fma.rn.f32x2 %0, %1, %2, %0;" : "+l"(c) : "l"(a), "l"(b));
}
__device__ __forceinline__ float2 unpack_ff(unsigned long long v) {
    unsigned int lo, hi;
    asm("mov.b64 {%0, %1}, %2;" : "=r"(lo), "=r"(hi) : "l"(v));
    float2 f;
    f.x = __uint_as_float(lo);
    f.y = __uint_as_float(hi);
    return f;
}

// ---------------------------------------------------------------------------
// Tiled SGEMM with fused bias + activation.
//   C[M,N] = act(A[M,K] @ B[K,N] + bias[N])
//   ACT: 0 = none, 1 = relu, 2 = tanh
// A, B, C row-major. All dims divisible by block sizes (true for this problem).
// ---------------------------------------------------------------------------
template<int BM, int BN, int BK, int TM, int TN, int ACT>
__global__ void __launch_bounds__(256, 2) sgemm_bias_act(
    const float* __restrict__ A, const float* __restrict__ B,
    const float* __restrict__ bias, float* __restrict__ C,
    int M, int N, int K)
{
    constexpr int TX = BN / TN;                // threads along N
    constexpr int TY = BM / TM;                // threads along M
    static_assert(TX * TY == 256, "need 256 threads");
    static_assert(TM % 4 == 0 && TN % 2 == 0, "frag shape");
    constexpr int A_LOADERS = BM * BK / 4;     // one float4 per loader
    constexpr int B_LOADERS = BK * BN / 4;

    __shared__ __align__(16) float As[BK][BM];
    __shared__ __align__(16) float Bs[BK][BN];

    const int tid = threadIdx.x;
    const int tx = tid % TX;
    const int ty = tid / TX;
    const int rowBase = blockIdx.y * BM;
    const int colBase = blockIdx.x * BN;

    // global-load mapping
    const int aRow = tid / (BK / 4);
    const int aK   = (tid % (BK / 4)) * 4;
    const int bRow = tid / (BN / 4);
    const int bCol = (tid % (BN / 4)) * 4;

    const float* Aptr = A + (long)(rowBase + aRow) * K + aK;
    const float* Bptr = B + (long)bRow * N + colBase + bCol;

    unsigned long long acc[TM][TN / 2];
    #pragma unroll
    for (int i = 0; i < TM; i++)
        #pragma unroll
        for (int j = 0; j < TN / 2; j++)
            acc[i][j] = 0ull;                  // {0.f, 0.f}

    for (int k0 = 0; k0 < K; k0 += BK) {
        if (A_LOADERS == 256 || tid < A_LOADERS) {
            float4 av = *(const float4*)(Aptr + k0);
            As[aK + 0][aRow] = av.x;
            As[aK + 1][aRow] = av.y;
            As[aK + 2][aRow] = av.z;
            As[aK + 3][aRow] = av.w;
        }
        if (B_LOADERS == 256 || tid < B_LOADERS) {
            *(float4*)&Bs[bRow][bCol] = *(const float4*)(Bptr + (long)k0 * N);
        }
        __syncthreads();

        #pragma unroll
        for (int kk = 0; kk < BK; kk++) {
            float a[TM];
            #pragma unroll
            for (int i = 0; i < TM; i += 4) {
                float4 v = *(const float4*)&As[kk][ty * TM + i];
                a[i + 0] = v.x; a[i + 1] = v.y; a[i + 2] = v.z; a[i + 3] = v.w;
            }
            unsigned long long b2[TN / 2];
            #pragma unroll
            for (int j = 0; j < TN / 2; j++)
                b2[j] = *(const unsigned long long*)&Bs[kk][tx * TN + 2 * j];
            #pragma unroll
            for (int i = 0; i < TM; i++) {
                unsigned long long a2 = pack_ff(a[i]);
                #pragma unroll
                for (int j = 0; j < TN / 2; j++)
                    ffma2(acc[i][j], a2, b2[j]);
            }
        }
        __syncthreads();
    }

    // epilogue: bias + activation, write C
    #pragma unroll
    for (int i = 0; i < TM; i++) {
        const int r = rowBase + ty * TM + i;
        #pragma unroll
        for (int j = 0; j < TN / 2; j++) {
            const int c = colBase + tx * TN + 2 * j;
            float2 v = unpack_ff(acc[i][j]);
            v.x += bias[c];
            v.y += bias[c + 1];
            if (ACT == 1) { v.x = fmaxf(v.x, 0.f); v.y = fmaxf(v.y, 0.f); }
            if (ACT == 2) { v.x = tanhf(v.x);      v.y = tanhf(v.y);      }
            C[(long)r * N + c]     = v.x;
            C[(long)r * N + c + 1] = v.y;
        }
    }
}

// ---------------------------------------------------------------------------
// out += sum_n sum_w q[n][w] * Wh[w]   (mean_w == 1 identically, see analysis)
// grid: 64 blocks x 256 threads, 128 rows per block
// ---------------------------------------------------------------------------
__global__ void reduce_out(const float* __restrict__ q,
                           const float* __restrict__ Wh,
                           float* __restrict__ out)
{
    const int tid = threadIdx.x;
    const int w  = tid & 63;       // column
    const int rl = tid >> 6;       // row lane 0..3
    const int rowBase = blockIdx.x * 128;

    float s = 0.f;
    #pragma unroll 8
    for (int r = rl; r < 128; r += 4)
        s += q[(rowBase + r) * W_DIM + w];
    s *= Wh[w];

    // block reduction
    #pragma unroll
    for (int o = 16; o > 0; o >>= 1)
        s += __shfl_down_sync(0xffffffffu, s, o);

    __shared__ float red[8];
    if ((tid & 31) == 0) red[tid >> 5] = s;
    __syncthreads();
    if (tid < 32) {
        float v = (tid < 8) ? red[tid] : 0.f;
        #pragma unroll
        for (int o = 4; o > 0; o >>= 1)
            v += __shfl_down_sync(0xffffffffu, v, o);
        if (tid == 0) atomicAdd(out, v);
    }
}

__global__ void init_out(float* __restrict__ out, const float* __restrict__ bh)
{
    if (threadIdx.x == 0) out[0] = bh[0];
}

// ---------------------------------------------------------------------------
// kernel_launch
// inputs (metadata order): state_batch, W1, b1, W2, b2, Wq, bq, Wh, bh
// ---------------------------------------------------------------------------
extern "C" void kernel_launch(void* const* d_in, const int* in_sizes, int n_in,
                              void* d_out, int out_size)
{
    const float* X  = (const float*)d_in[0];
    const float* W1 = (const float*)d_in[1];
    const float* b1 = (const float*)d_in[2];
    const float* W2 = (const float*)d_in[3];
    const float* b2 = (const float*)d_in[4];
    const float* Wq = (const float*)d_in[5];
    const float* bq = (const float*)d_in[6];
    const float* Wh = (const float*)d_in[7];
    const float* bh = (const float*)d_in[8];
    float* out = (float*)d_out;

    float *h1, *h2, *q;
    cudaGetSymbolAddress((void**)&h1, g_h1);
    cudaGetSymbolAddress((void**)&h2, g_h2);
    cudaGetSymbolAddress((void**)&q,  g_q);

    // out = bh (also clears the 0xAA poison)
    init_out<<<1, 32>>>(out, bh);

    // h1 = relu(X @ W1 + b1)        [8192,512] x [512,256]
    sgemm_bias_act<128, 128, 8, 8, 8, 1>
        <<<dim3(H_DIM / 128, N_ROWS / 128), 256>>>(X, W1, b1, h1,
                                                   N_ROWS, H_DIM, F_IN);

    // h2 = relu(h1 @ W2 + b2)       [8192,256] x [256,256]
    sgemm_bias_act<128, 128, 8, 8, 8, 1>
        <<<dim3(H_DIM / 128, N_ROWS / 128), 256>>>(h1, W2, b2, h2,
                                                   N_ROWS, H_DIM, H_DIM);

    // q = tanh(h2 @ Wq + bq)        [8192,256] x [256,64]
    sgemm_bias_act<64, 64, 8, 4, 4, 2>
        <<<dim3(W_DIM / 64, N_ROWS / 64), 256>>>(h2, Wq, bq, q,
                                                 N_ROWS, W_DIM, H_DIM);

    // out += sum(q) @ Wh   (mean neighbor weight is identically 1.0)
    reduce_out<<<64, 256>>>(q, Wh, out);
}

// round 7
// speedup vs baseline: 1.4189x; 1.4189x over previous
#include <cuda_runtime.h>
#include <math.h>

#define N_ROWS 8192
#define F_IN   512
#define H_DIM  256
#define W_DIM  64

// Scratch (device globals: allocation-free per harness rules)
static __device__ float g_h1[N_ROWS * H_DIM];   // 8 MB
static __device__ float g_h2[N_ROWS * H_DIM];   // 8 MB

// ---------------------------------------------------------------------------
// f32x2 packed helpers (FFMA2: 2 MACs per instruction on sm_103a)
// ---------------------------------------------------------------------------
__device__ __forceinline__ unsigned long long pack_ff(float a) {
    unsigned long long r;
    unsigned int u = __float_as_uint(a);
    asm("mov.b64 %0, {%1, %1};" : "=l"(r) : "r"(u));
    return r;
}
__device__ __forceinline__ void ffma2(unsigned long long &c,
                                      unsigned long long a,
                                      unsigned long long b) {
    asm("fma.rn.f32x2 %0, %1, %2, %0;" : "+l"(c) : "l"(a), "l"(b));
}
__device__ __forceinline__ float2 unpack_ff(unsigned long long v) {
    unsigned int lo, hi;
    asm("mov.b64 {%0, %1}, %2;" : "=r"(lo), "=r"(hi) : "l"(v));
    float2 f;
    f.x = __uint_as_float(lo);
    f.y = __uint_as_float(hi);
    return f;
}

// ---------------------------------------------------------------------------
// GEMM + bias + ReLU.  C[M,N] = relu(A[M,K] @ B[K,N] + bias[N])
// BM=128, BN=64, BK=16, TM=8, TN=4, 256 threads, 2 CTAs/SM.
// Register-prefetch double buffering on the global loads.
// ---------------------------------------------------------------------------
#define BM 128
#define BN 64
#define BK 16
#define TM 8
#define TN 4
#define TX (BN / TN)   // 16
#define TY (BM / TM)   // 16

__global__ void __launch_bounds__(256, 2) sgemm_relu(
    const float* __restrict__ A, const float* __restrict__ B,
    const float* __restrict__ bias, float* __restrict__ C,
    int M, int N, int K)
{
    __shared__ __align__(16) float As[BK][BM];
    __shared__ __align__(16) float Bs[BK][BN];

    const int tid = threadIdx.x;
    const int tx = tid % TX;
    const int ty = tid / TX;
    const int rowBase = blockIdx.y * BM;
    const int colBase = blockIdx.x * BN;

    // global-load mapping: A = 512 float4 per tile -> 2 per thread
    const int aRow = tid / (BK / 4);          // 0..63
    const int aK   = (tid % (BK / 4)) * 4;    // 0,4,8,12
    const int bRow = tid / (BN / 4);          // 0..15
    const int bCol = (tid % (BN / 4)) * 4;

    const float* Aptr0 = A + (long)(rowBase + aRow) * K + aK;
    const float* Aptr1 = Aptr0 + 64L * K;
    const float* Bptr  = B + (long)bRow * N + colBase + bCol;

    unsigned long long acc[TM][TN / 2];
    #pragma unroll
    for (int i = 0; i < TM; i++)
        #pragma unroll
        for (int j = 0; j < TN / 2; j++)
            acc[i][j] = 0ull;

    // prefetch k0 = 0
    float4 pa0 = *(const float4*)(Aptr0);
    float4 pa1 = *(const float4*)(Aptr1);
    float4 pb  = *(const float4*)(Bptr);

    for (int k0 = 0; k0 < K; k0 += BK) {
        // stage registers -> smem
        As[aK + 0][aRow]      = pa0.x;
        As[aK + 1][aRow]      = pa0.y;
        As[aK + 2][aRow]      = pa0.z;
        As[aK + 3][aRow]      = pa0.w;
        As[aK + 0][aRow + 64] = pa1.x;
        As[aK + 1][aRow + 64] = pa1.y;
        As[aK + 2][aRow + 64] = pa1.z;
        As[aK + 3][aRow + 64] = pa1.w;
        *(float4*)&Bs[bRow][bCol] = pb;
        __syncthreads();

        // prefetch next slab while computing this one
        if (k0 + BK < K) {
            pa0 = *(const float4*)(Aptr0 + k0 + BK);
            pa1 = *(const float4*)(Aptr1 + k0 + BK);
            pb  = *(const float4*)(Bptr + (long)(k0 + BK) * N);
        }

        #pragma unroll
        for (int kk = 0; kk < BK; kk++) {
            float a[TM];
            #pragma unroll
            for (int i = 0; i < TM; i += 4) {
                float4 v = *(const float4*)&As[kk][ty * TM + i];
                a[i + 0] = v.x; a[i + 1] = v.y; a[i + 2] = v.z; a[i + 3] = v.w;
            }
            unsigned long long b2[TN / 2];
            #pragma unroll
            for (int j = 0; j < TN / 2; j++)
                b2[j] = *(const unsigned long long*)&Bs[kk][tx * TN + 2 * j];
            #pragma unroll
            for (int i = 0; i < TM; i++) {
                unsigned long long a2 = pack_ff(a[i]);
                #pragma unroll
                for (int j = 0; j < TN / 2; j++)
                    ffma2(acc[i][j], a2, b2[j]);
            }
        }
        __syncthreads();
    }

    // epilogue: bias + relu, vector store
    const int c = colBase + tx * TN;
    const float4 bv = *(const float4*)&bias[c];
    #pragma unroll
    for (int i = 0; i < TM; i++) {
        const int r = rowBase + ty * TM + i;
        float2 v0 = unpack_ff(acc[i][0]);
        float2 v1 = unpack_ff(acc[i][1]);
        float4 o;
        o.x = fmaxf(v0.x + bv.x, 0.f);
        o.y = fmaxf(v0.y + bv.y, 0.f);
        o.z = fmaxf(v1.x + bv.z, 0.f);
        o.w = fmaxf(v1.y + bv.w, 0.f);
        *(float4*)&C[(long)r * N + c] = o;
    }
}

// ---------------------------------------------------------------------------
// Fused final stage:
//   out += sum_rows( tanh(h2 @ Wq + bq) * Wh )
// (mean neighbor weight is identically 1.0 — wsum/deg == 1, deg==0 -> 1)
// GM=32 rows per block, full N=64, K=256. 256 CTAs, block-reduce + atomicAdd.
// ---------------------------------------------------------------------------
#define GM 32
#define GTM 2

__global__ void __launch_bounds__(256, 2) gemm3_tanh_dot(
    const float* __restrict__ A,   // h2 [N_ROWS, 256]
    const float* __restrict__ Wq,  // [256, 64]
    const float* __restrict__ bq,  // [64]
    const float* __restrict__ Wh,  // [64]
    float* __restrict__ out)
{
    __shared__ __align__(16) float As[BK][GM];
    __shared__ __align__(16) float Bs[BK][BN];
    __shared__ float red[8];

    const int tid = threadIdx.x;
    const int tx = tid % TX;            // 0..15, 4 cols each
    const int ty = tid / TX;            // 0..15, 2 rows each
    const int rowBase = blockIdx.x * GM;
    const int K = H_DIM;

    // A loaders: GM*BK/4 = 128 float4 -> tid < 128
    const int aRow = tid / (BK / 4);    // 0..31 (for tid<128)
    const int aK   = (tid % (BK / 4)) * 4;
    const int bRow = tid / (BN / 4);
    const int bCol = (tid % (BN / 4)) * 4;

    const float* Aptr = A + (long)(rowBase + aRow) * K + aK;
    const float* Bptr = Wq + (long)bRow * BN + bCol;

    unsigned long long acc[GTM][TN / 2];
    #pragma unroll
    for (int i = 0; i < GTM; i++)
        #pragma unroll
        for (int j = 0; j < TN / 2; j++)
            acc[i][j] = 0ull;

    float4 pa = make_float4(0.f, 0.f, 0.f, 0.f);
    if (tid < 128) pa = *(const float4*)(Aptr);
    float4 pb = *(const float4*)(Bptr);

    for (int k0 = 0; k0 < K; k0 += BK) {
        if (tid < 128) {
            As[aK + 0][aRow] = pa.x;
            As[aK + 1][aRow] = pa.y;
            As[aK + 2][aRow] = pa.z;
            As[aK + 3][aRow] = pa.w;
        }
        *(float4*)&Bs[bRow][bCol] = pb;
        __syncthreads();

        if (k0 + BK < K) {
            if (tid < 128) pa = *(const float4*)(Aptr + k0 + BK);
            pb = *(const float4*)(Bptr + (long)(k0 + BK) * BN);
        }

        #pragma unroll
        for (int kk = 0; kk < BK; kk++) {
            float a0 = As[kk][ty * GTM + 0];
            float a1 = As[kk][ty * GTM + 1];
            unsigned long long b2[TN / 2];
            #pragma unroll
            for (int j = 0; j < TN / 2; j++)
                b2[j] = *(const unsigned long long*)&Bs[kk][tx * TN + 2 * j];
            unsigned long long a2;
            a2 = pack_ff(a0);
            ffma2(acc[0][0], a2, b2[0]);
            ffma2(acc[0][1], a2, b2[1]);
            a2 = pack_ff(a1);
            ffma2(acc[1][0], a2, b2[0]);
            ffma2(acc[1][1], a2, b2[1]);
        }
        __syncthreads();
    }

    // epilogue: tanh + dot with Wh, then block reduce
    const int c = tx * TN;
    const float4 bq4 = *(const float4*)&bq[c];
    const float4 wh4 = *(const float4*)&Wh[c];
    float s = 0.f;
    #pragma unroll
    for (int i = 0; i < GTM; i++) {
        float2 v0 = unpack_ff(acc[i][0]);
        float2 v1 = unpack_ff(acc[i][1]);
        s += tanhf(v0.x + bq4.x) * wh4.x;
        s += tanhf(v0.y + bq4.y) * wh4.y;
        s += tanhf(v1.x + bq4.z) * wh4.z;
        s += tanhf(v1.y + bq4.w) * wh4.w;
    }
    #pragma unroll
    for (int o = 16; o > 0; o >>= 1)
        s += __shfl_down_sync(0xffffffffu, s, o);
    if ((tid & 31) == 0) red[tid >> 5] = s;
    __syncthreads();
    if (tid == 0) {
        float t = 0.f;
        #pragma unroll
        for (int i = 0; i < 8; i++) t += red[i];
        atomicAdd(out, t);
    }
}

__global__ void init_out(float* __restrict__ out, const float* __restrict__ bh)
{
    if (threadIdx.x == 0) out[0] = bh[0];
}

// ---------------------------------------------------------------------------
// kernel_launch
// inputs (metadata order): state_batch, W1, b1, W2, b2, Wq, bq, Wh, bh
// ---------------------------------------------------------------------------
extern "C" void kernel_launch(void* const* d_in, const int* in_sizes, int n_in,
                              void* d_out, int out_size)
{
    const float* X  = (const float*)d_in[0];
    const float* W1 = (const float*)d_in[1];
    const float* b1 = (const float*)d_in[2];
    const float* W2 = (const float*)d_in[3];
    const float* b2 = (const float*)d_in[4];
    const float* Wq = (const float*)d_in[5];
    const float* bq = (const float*)d_in[6];
    const float* Wh = (const float*)d_in[7];
    const float* bh = (const float*)d_in[8];
    float* out = (float*)d_out;

    float *h1, *h2;
    cudaGetSymbolAddress((void**)&h1, g_h1);
    cudaGetSymbolAddress((void**)&h2, g_h2);

    // out = bh (also clears the 0xAA poison)
    init_out<<<1, 32>>>(out, bh);

    // h1 = relu(X @ W1 + b1)        [8192,512] x [512,256]   grid 256
    sgemm_relu<<<dim3(H_DIM / BN, N_ROWS / BM), 256>>>(X, W1, b1, h1,
                                                       N_ROWS, H_DIM, F_IN);

    // h2 = relu(h1 @ W2 + b2)       [8192,256] x [256,256]   grid 256
    sgemm_relu<<<dim3(H_DIM / BN, N_ROWS / BM), 256>>>(h1, W2, b2, h2,
                                                       N_ROWS, H_DIM, H_DIM);

    // out += sum_rows( tanh(h2 @ Wq + bq) * Wh )             grid 256
    gemm3_tanh_dot<<<N_ROWS / GM, 256>>>(h2, Wq, bq, Wh, out);
}

// round 8
// speedup vs baseline: 1.6213x; 1.1427x over previous
#include <cuda_runtime.h>
#include <math.h>

#define NROWS 8192
#define KIN   512
#define HD    256
#define WD    64
#define BK    8
#define BM    32      // rows per CTA
#define TM    8       // rows per thread
#define TN    8       // cols per thread (stage 1/2)

// ---------------------------------------------------------------------------
// f32x2 packed helpers (FFMA2: 2 MACs per instruction on sm_103a)
// ---------------------------------------------------------------------------
__device__ __forceinline__ unsigned long long pack_ff(float a) {
    unsigned long long r;
    unsigned int u = __float_as_uint(a);
    asm("mov.b64 %0, {%1, %1};" : "=l"(r) : "r"(u));
    return r;
}
__device__ __forceinline__ void ffma2(unsigned long long &c,
                                      unsigned long long a,
                                      unsigned long long b) {
    asm("fma.rn.f32x2 %0, %1, %2, %0;" : "+l"(c) : "l"(a), "l"(b));
}
__device__ __forceinline__ float2 unpack_ff(unsigned long long v) {
    unsigned int lo, hi;
    asm("mov.b64 {%0, %1}, %2;" : "=r"(lo), "=r"(hi) : "l"(v));
    float2 f;
    f.x = __uint_as_float(lo);
    f.y = __uint_as_float(hi);
    return f;
}

// ---------------------------------------------------------------------------
// Fully fused network: per CTA, 32 rows flow through all three layers.
//   h1 = relu(X@W1+b1)  -> smem
//   h2 = relu(h1@W2+b2) -> smem (overwrites h1)
//   out += sum( tanh(h2@Wq+bq) * Wh )   [mean neighbor weight == 1.0]
// 128 threads: tx = lane (32 cols of 8), ty = warp (4 row-groups of 8).
// Weight slabs staged in a column-block-swizzled buffer (2-way max conflicts).
// ---------------------------------------------------------------------------
__global__ void __launch_bounds__(128, 2) fused_net(
    const float* __restrict__ X,
    const float* __restrict__ W1, const float* __restrict__ b1,
    const float* __restrict__ W2, const float* __restrict__ b2,
    const float* __restrict__ Wq, const float* __restrict__ bq,
    const float* __restrict__ Wh, float* __restrict__ out)
{
    __shared__ __align__(16) float h1s[BM * HD];     // 32 KB activations
    __shared__ __align__(16) float BsW[32 * 68];     // swizzled weight slab
    __shared__ __align__(16) float Bs3[BK * WD];     // stage-3 Wq slab
    __shared__ __align__(16) float As1[BM * BK];     // stage-1 X slab
    __shared__ float red[4];

    const int tid = threadIdx.x;
    const int tx  = tid & 31;
    const int ty  = tid >> 5;
    const int rowBase = blockIdx.x * BM;

    // loader mappings
    const int aRow = tid >> 1;                 // 0..63 (tid<64 used)
    const int aK   = (tid & 1) * 4;
    const int lcol = (tid & 63) * 4;           // weight col
    const int cbS  = (lcol >> 3) * 68 + (lcol & 7);   // swizzled dest base
    const int rowG = (tid >> 6) * 4;           // 0 or 4
    const int wRow = tid >> 4;                 // 0..7 (stage 3)
    const int wCol = (tid & 15) * 4;

    unsigned long long acc[TM][TN / 2];

    // ======================= stage 1: h1 = relu(X@W1+b1), K=512 ============
    #pragma unroll
    for (int i = 0; i < TM; i++)
        #pragma unroll
        for (int j = 0; j < TN / 2; j++) acc[i][j] = 0ull;

    float4 pa;
    float4 pb[4];
    if (tid < 64)
        pa = *(const float4*)(X + (long)(rowBase + aRow) * KIN + aK);
    #pragma unroll
    for (int r = 0; r < 4; r++)
        pb[r] = *(const float4*)(W1 + (long)(rowG + r) * HD + lcol);

    for (int k0 = 0; k0 < KIN; k0 += BK) {
        if (tid < 64) *(float4*)&As1[aRow * BK + aK] = pa;
        #pragma unroll
        for (int r = 0; r < 4; r++)
            *(float4*)&BsW[cbS + (rowG + r) * 8] = pb[r];
        __syncthreads();

        if (k0 + BK < KIN) {
            if (tid < 64)
                pa = *(const float4*)(X + (long)(rowBase + aRow) * KIN + k0 + BK + aK);
            #pragma unroll
            for (int r = 0; r < 4; r++)
                pb[r] = *(const float4*)(W1 + (long)(k0 + BK + rowG + r) * HD + lcol);
        }

        #pragma unroll
        for (int kp = 0; kp < BK / 2; kp++) {
            float2 ap[TM];
            #pragma unroll
            for (int i = 0; i < TM; i++)
                ap[i] = *(const float2*)&As1[(ty * TM + i) * BK + 2 * kp];
            #pragma unroll
            for (int q = 0; q < 2; q++) {
                const int kk = 2 * kp + q;
                unsigned long long b2[TN / 2];
                #pragma unroll
                for (int j = 0; j < TN / 2; j++)
                    b2[j] = *(const unsigned long long*)&BsW[tx * 68 + kk * 8 + 2 * j];
                #pragma unroll
                for (int i = 0; i < TM; i++) {
                    unsigned long long a2 = pack_ff(q ? ap[i].y : ap[i].x);
                    #pragma unroll
                    for (int j = 0; j < TN / 2; j++) ffma2(acc[i][j], a2, b2[j]);
                }
            }
        }
        __syncthreads();
    }

    // prefetch first W2 slab (overlap with epilogue)
    #pragma unroll
    for (int r = 0; r < 4; r++)
        pb[r] = *(const float4*)(W2 + (long)(rowG + r) * HD + lcol);

    // epilogue 1 -> h1s
    {
        const int c = tx * 8;
        const float4 bva = *(const float4*)&b1[c];
        const float4 bvb = *(const float4*)&b1[c + 4];
        #pragma unroll
        for (int i = 0; i < TM; i++) {
            const int r = ty * TM + i;
            float2 v0 = unpack_ff(acc[i][0]);
            float2 v1 = unpack_ff(acc[i][1]);
            float2 v2 = unpack_ff(acc[i][2]);
            float2 v3 = unpack_ff(acc[i][3]);
            float4 o0 = make_float4(fmaxf(v0.x + bva.x, 0.f), fmaxf(v0.y + bva.y, 0.f),
                                    fmaxf(v1.x + bva.z, 0.f), fmaxf(v1.y + bva.w, 0.f));
            float4 o1 = make_float4(fmaxf(v2.x + bvb.x, 0.f), fmaxf(v2.y + bvb.y, 0.f),
                                    fmaxf(v3.x + bvb.z, 0.f), fmaxf(v3.y + bvb.w, 0.f));
            *(float4*)&h1s[r * HD + c]     = o0;
            *(float4*)&h1s[r * HD + c + 4] = o1;
        }
    }
    __syncthreads();

    // ======================= stage 2: h2 = relu(h1@W2+b2), K=256 ===========
    #pragma unroll
    for (int i = 0; i < TM; i++)
        #pragma unroll
        for (int j = 0; j < TN / 2; j++) acc[i][j] = 0ull;

    for (int k0 = 0; k0 < HD; k0 += BK) {
        #pragma unroll
        for (int r = 0; r < 4; r++)
            *(float4*)&BsW[cbS + (rowG + r) * 8] = pb[r];
        __syncthreads();

        if (k0 + BK < HD) {
            #pragma unroll
            for (int r = 0; r < 4; r++)
                pb[r] = *(const float4*)(W2 + (long)(k0 + BK + rowG + r) * HD + lcol);
        }

        #pragma unroll
        for (int kp = 0; kp < BK / 2; kp++) {
            float2 ap[TM];
            #pragma unroll
            for (int i = 0; i < TM; i++)
                ap[i] = *(const float2*)&h1s[(ty * TM + i) * HD + k0 + 2 * kp];
            #pragma unroll
            for (int q = 0; q < 2; q++) {
                const int kk = 2 * kp + q;
                unsigned long long b2[TN / 2];
                #pragma unroll
                for (int j = 0; j < TN / 2; j++)
                    b2[j] = *(const unsigned long long*)&BsW[tx * 68 + kk * 8 + 2 * j];
                #pragma unroll
                for (int i = 0; i < TM; i++) {
                    unsigned long long a2 = pack_ff(q ? ap[i].y : ap[i].x);
                    #pragma unroll
                    for (int j = 0; j < TN / 2; j++) ffma2(acc[i][j], a2, b2[j]);
                }
            }
        }
        __syncthreads();
    }

    // prefetch first Wq slab
    float4 pw = *(const float4*)(Wq + (long)wRow * WD + wCol);

    // epilogue 2 -> h1s (all stage-2 reads are done: loop ended on a sync)
    {
        const int c = tx * 8;
        const float4 bva = *(const float4*)&b2[c];
        const float4 bvb = *(const float4*)&b2[c + 4];
        #pragma unroll
        for (int i = 0; i < TM; i++) {
            const int r = ty * TM + i;
            float2 v0 = unpack_ff(acc[i][0]);
            float2 v1 = unpack_ff(acc[i][1]);
            float2 v2 = unpack_ff(acc[i][2]);
            float2 v3 = unpack_ff(acc[i][3]);
            float4 o0 = make_float4(fmaxf(v0.x + bva.x, 0.f), fmaxf(v0.y + bva.y, 0.f),
                                    fmaxf(v1.x + bva.z, 0.f), fmaxf(v1.y + bva.w, 0.f));
            float4 o1 = make_float4(fmaxf(v2.x + bvb.x, 0.f), fmaxf(v2.y + bvb.y, 0.f),
                                    fmaxf(v3.x + bvb.z, 0.f), fmaxf(v3.y + bvb.w, 0.f));
            *(float4*)&h1s[r * HD + c]     = o0;
            *(float4*)&h1s[r * HD + c + 4] = o1;
        }
    }
    __syncthreads();

    // ======== stage 3: out += sum(tanh(h2@Wq+bq)*Wh), K=256, N=64 ==========
    unsigned long long acc3[TM];
    #pragma unroll
    for (int i = 0; i < TM; i++) acc3[i] = 0ull;

    for (int k0 = 0; k0 < HD; k0 += BK) {
        *(float4*)&Bs3[wRow * WD + wCol] = pw;
        __syncthreads();

        if (k0 + BK < HD)
            pw = *(const float4*)(Wq + (long)(k0 + BK + wRow) * WD + wCol);

        #pragma unroll
        for (int kp = 0; kp < BK / 2; kp++) {
            float2 ap[TM];
            #pragma unroll
            for (int i = 0; i < TM; i++)
                ap[i] = *(const float2*)&h1s[(ty * TM + i) * HD + k0 + 2 * kp];
            #pragma unroll
            for (int q = 0; q < 2; q++) {
                const int kk = 2 * kp + q;
                unsigned long long b2 =
                    *(const unsigned long long*)&Bs3[kk * WD + tx * 2];
                #pragma unroll
                for (int i = 0; i < TM; i++) {
                    unsigned long long a2 = pack_ff(q ? ap[i].y : ap[i].x);
                    ffma2(acc3[i], a2, b2);
                }
            }
        }
        __syncthreads();
    }

    // epilogue 3: tanh + dot Wh + block reduce + atomicAdd
    {
        const float2 bqv = *(const float2*)&bq[tx * 2];
        const float2 whv = *(const float2*)&Wh[tx * 2];
        float s = 0.f;
        #pragma unroll
        for (int i = 0; i < TM; i++) {
            float2 v = unpack_ff(acc3[i]);
            s += tanhf(v.x + bqv.x) * whv.x;
            s += tanhf(v.y + bqv.y) * whv.y;
        }
        #pragma unroll
        for (int o = 16; o > 0; o >>= 1)
            s += __shfl_down_sync(0xffffffffu, s, o);
        if (tx == 0) red[ty] = s;
        __syncthreads();
        if (tid == 0)
            atomicAdd(out, red[0] + red[1] + red[2] + red[3]);
    }
}

__global__ void init_out(float* __restrict__ out, const float* __restrict__ bh)
{
    if (threadIdx.x == 0) out[0] = bh[0];
}

// ---------------------------------------------------------------------------
// kernel_launch
// inputs (metadata order): state_batch, W1, b1, W2, b2, Wq, bq, Wh, bh
// ---------------------------------------------------------------------------
extern "C" void kernel_launch(void* const* d_in, const int* in_sizes, int n_in,
                              void* d_out, int out_size)
{
    const float* X  = (const float*)d_in[0];
    const float* W1 = (const float*)d_in[1];
    const float* b1 = (const float*)d_in[2];
    const float* W2 = (const float*)d_in[3];
    const float* b2 = (const float*)d_in[4];
    const float* Wq = (const float*)d_in[5];
    const float* bq = (const float*)d_in[6];
    const float* Wh = (const float*)d_in[7];
    const float* bh = (const float*)d_in[8];
    float* out = (float*)d_out;

    // out = bh (also clears the 0xAA poison)
    init_out<<<1, 32>>>(out, bh);

    // whole network in one kernel: 256 CTAs x 128 threads, 32 rows each
    fused_net<<<NROWS / BM, 128>>>(X, W1, b1, W2, b2, Wq, bq, Wh, out);
}